// round 16
// baseline (speedup 1.0000x reference)
#include <cuda_runtime.h>
#include <cuda_fp16.h>
#include <mma.h>
#include <math.h>

using namespace nvcuda;

#define L_SEQ 2048
#define H_DIM 2048
#define G3H   6144
#define NCTA  147
#define CHUNK 14      // h elements per CTA (147*14 = 2058 >= 2048)
#define TPB   512     // 16 warps; warps 0..13 own j = cta*14 + warp

// -------- device-global scratch (no allocations allowed) --------
__device__ float g_gi[(size_t)L_SEQ * G3H];        // 48 MB: raw x@W_ih^T (bias added in kernel B)
__device__ __align__(16) __half g_h16[2][H_DIM];   // double-buffered fp16 h
__device__ unsigned int g_sync;                    // monotonic arrival counter
__device__ __align__(16) __half g_x16[(size_t)L_SEQ * H_DIM];   // 8 MB fp16 x
__device__ __align__(16) __half g_w16[(size_t)G3H * H_DIM];     // 24 MB fp16 w_ih

__device__ __forceinline__ __half2 u2h2(unsigned u) {
    return *reinterpret_cast<__half2*>(&u);
}

// fast sigmoid / tanh via MUFU (ex2 + rcp), rel err ~1e-6
__device__ __forceinline__ float fsig(float x) {
    float e, r;
    asm("ex2.approx.ftz.f32 %0, %1;" : "=f"(e) : "f"(-1.4426950408889634f * x));
    asm("rcp.approx.ftz.f32 %0, %1;" : "=f"(r) : "f"(1.0f + e));
    return r;
}
__device__ __forceinline__ float ftanh(float x) {
    float e, r;
    asm("ex2.approx.ftz.f32 %0, %1;" : "=f"(e) : "f"(2.8853900817779268f * x));  // e^(2x)
    asm("rcp.approx.ftz.f32 %0, %1;" : "=f"(r) : "f"(1.0f + e));
    return 1.0f - 2.0f * r;
}

// ============================================================
// fp32 -> fp16 conversion. Device globals referenced from DEVICE
// code only (host-side __device__ symbol args was the R10/R11 bug).
// ============================================================
__device__ __forceinline__ void cvt_body(const float* __restrict__ src,
                                         __half* __restrict__ dst, int i) {
    float4 f0 = reinterpret_cast<const float4*>(src)[2 * i];
    float4 f1 = reinterpret_cast<const float4*>(src)[2 * i + 1];
    __half2 h0 = __floats2half2_rn(f0.x, f0.y);
    __half2 h1 = __floats2half2_rn(f0.z, f0.w);
    __half2 h2 = __floats2half2_rn(f1.x, f1.y);
    __half2 h3 = __floats2half2_rn(f1.z, f1.w);
    uint4 v;
    v.x = *reinterpret_cast<unsigned*>(&h0);
    v.y = *reinterpret_cast<unsigned*>(&h1);
    v.z = *reinterpret_cast<unsigned*>(&h2);
    v.w = *reinterpret_cast<unsigned*>(&h3);
    reinterpret_cast<uint4*>(dst)[i] = v;
}

__global__ void cvt_x_kernel(const float* __restrict__ src) {
    int i = blockIdx.x * blockDim.x + threadIdx.x;
    if (i == 0) g_sync = 0u;
    if (i < L_SEQ * H_DIM / 8) cvt_body(src, g_x16, i);
}

__global__ void cvt_w_kernel(const float* __restrict__ src) {
    int i = blockIdx.x * blockDim.x + threadIdx.x;
    if (i < G3H * H_DIM / 8) cvt_body(src, g_w16, i);
}

// ============================================================
// Kernel A: tensor-core GEMM via wmma (R12-proven, unchanged).
// g_gi[t][c] = sum_k x16[t][k] * w16[c][k]   (raw product, no bias)
// ============================================================
#define GM 128
#define GN 64
#define GK 32
#define GP (GK + 8)   // SMEM pitch in halfs

__global__ void __launch_bounds__(256) gemm_gi_kernel() {
    __shared__ __half Asm[GM][GP];
    __shared__ __half Bsm[GN][GP];

    const int bm = blockIdx.y * GM;      // time rows
    const int bn = blockIdx.x * GN;      // gate cols
    const int tid  = threadIdx.x;
    const int warp = tid >> 5;
    const int wm = warp >> 1;            // 0..3
    const int wn = warp & 1;             // 0..1

    wmma::fragment<wmma::accumulator, 16, 16, 16, float> fc[2][2];
#pragma unroll
    for (int i = 0; i < 2; i++)
#pragma unroll
        for (int jn = 0; jn < 2; jn++)
            wmma::fill_fragment(fc[i][jn], 0.0f);

    const int arow = tid >> 1, acolh = (tid & 1) * 16;   // A: 128 rows x 32 halfs
    const int brow = tid >> 2, bcolh = (tid & 3) * 8;    // B: 64 rows x 32 halfs

    for (int k0 = 0; k0 < H_DIM; k0 += GK) {
        {
            const uint4* asrc = reinterpret_cast<const uint4*>(
                &g_x16[(size_t)(bm + arow) * H_DIM + k0 + acolh]);
            uint4 av0 = asrc[0], av1 = asrc[1];
            *reinterpret_cast<uint4*>(&Asm[arow][acolh])     = av0;
            *reinterpret_cast<uint4*>(&Asm[arow][acolh + 8]) = av1;
            uint4 bv = *reinterpret_cast<const uint4*>(
                &g_w16[(size_t)(bn + brow) * H_DIM + k0 + bcolh]);
            *reinterpret_cast<uint4*>(&Bsm[brow][bcolh]) = bv;
        }
        __syncthreads();

#pragma unroll
        for (int kk = 0; kk < GK; kk += 16) {
            wmma::fragment<wmma::matrix_a, 16, 16, 16, __half, wmma::row_major> fa[2];
            wmma::fragment<wmma::matrix_b, 16, 16, 16, __half, wmma::col_major> fb[2];
#pragma unroll
            for (int i = 0; i < 2; i++)
                wmma::load_matrix_sync(fa[i], &Asm[wm * 32 + i * 16][kk], GP);
#pragma unroll
            for (int jn = 0; jn < 2; jn++)
                wmma::load_matrix_sync(fb[jn], &Bsm[wn * 32 + jn * 16][kk], GP);
#pragma unroll
            for (int i = 0; i < 2; i++)
#pragma unroll
                for (int jn = 0; jn < 2; jn++)
                    wmma::mma_sync(fc[i][jn], fa[i], fb[jn], fc[i][jn]);
        }
        __syncthreads();
    }

#pragma unroll
    for (int i = 0; i < 2; i++)
#pragma unroll
        for (int jn = 0; jn < 2; jn++) {
            int row = bm + wm * 32 + i * 16;
            int col = bn + wn * 32 + jn * 16;
            wmma::store_matrix_sync(&g_gi[(size_t)row * G3H + col], fc[i][jn],
                                    G3H, wmma::mem_row_major);
        }
}

// ============================================================
// Kernel B: persistent GRU recurrence (R15 structure).
// ONE change vs R15: geometry 128 CTAs x 16 busy warps ->
// 147 CTAs x 14 busy warps (warps 14,15 idle except barriers).
// Per-SM matvec work drops 16/14: fma floor 768 -> 672 cyc,
// crossbar 512 -> 448 cyc. Poll target becomes t*147.
// ============================================================
__global__ void __launch_bounds__(TPB, 1) gru_kernel(const float* __restrict__ w_hh,
                                                     const float* __restrict__ b_ih,
                                                     const float* __restrict__ b_hh,
                                                     float* __restrict__ out,
                                                     int out_elems) {
    __shared__ uint4 sH[H_DIM / 8];     // 2048 halfs = 4KB

    const int tid  = threadIdx.x;
    const int warp = tid >> 5;
    const int lane = tid & 31;
    const int j    = blockIdx.x * CHUNK + warp;
    const bool active = (warp < CHUNK) && (j < H_DIM);

    // ---- prologue: 3 rows of W_hh into 96 half2 registers ----
    __half2 w[3][8][4];
    if (active) {
#pragma unroll
        for (int g = 0; g < 3; g++) {
            const float* wr = w_hh + (size_t)(g * H_DIM + j) * H_DIM;
#pragma unroll
            for (int i = 0; i < 8; i++) {
                int k = i * 256 + lane * 8;
                float4 a = *reinterpret_cast<const float4*>(wr + k);
                float4 b = *reinterpret_cast<const float4*>(wr + k + 4);
                w[g][i][0] = __floats2half2_rn(a.x, a.y);
                w[g][i][1] = __floats2half2_rn(a.z, a.w);
                w[g][i][2] = __floats2half2_rn(b.x, b.y);
                w[g][i][3] = __floats2half2_rn(b.z, b.w);
            }
        }
    }

    float h_own = 0.0f;
    // lane-0 bias registers: r,z get b_ih+b_hh; n gets b_ih only,
    // with b_hh_n kept inside the reset-gate product (torch semantics).
    float bir = 0.f, biz = 0.f, bin = 0.f, bhn = 0.f;
    if (active && lane == 0) {
        bir = b_ih[j]             + b_hh[j];
        biz = b_ih[H_DIM + j]     + b_hh[H_DIM + j];
        bin = b_ih[2 * H_DIM + j];
        bhn = b_hh[2 * H_DIM + j];
    }
    const float* gi_ptr  = g_gi + j;
    float*       out_ptr = out + j;

    // ---- gi pipeline prologue: load step 0's values ----
    float ir = 0.f, iz = 0.f, inn = 0.f;
    if (active && lane == 0) {
        ir  = gi_ptr[0];
        iz  = gi_ptr[H_DIM];
        inn = gi_ptr[2 * H_DIM];
    }

    for (int t = 0; t < L_SEQ; t++) {
        // ---- issue NEXT step's gi loads (consumed next iteration) ----
        float nir = 0.f, niz = 0.f, ninn = 0.f;
        if (active && lane == 0 && t + 1 < L_SEQ) {
            const float* np = gi_ptr + G3H;
            nir  = np[0];
            niz  = np[H_DIM];
            ninn = np[2 * H_DIM];
        }

        if (t > 0) {
            // ---- chip-wide wait for step t's h (simple tid0 poll) ----
            if (tid == 0) {
                unsigned target = (unsigned)t * (unsigned)NCTA;
                unsigned v;
                do {
                    asm volatile("ld.acquire.gpu.global.u32 %0, [%1];"
                                 : "=r"(v) : "l"(&g_sync) : "memory");
                } while (v < target);
            }
            __syncthreads();
            // ---- stage h into SMEM: 256 lanes x uint4 = 4KB ----
            if (tid < H_DIM / 8)
                sH[tid] = __ldcg(reinterpret_cast<const uint4*>(&g_h16[t & 1][0]) + tid);
            __syncthreads();
        }

        // ---- matvec: 3 rows, weights in regs, h from SMEM.
        //      Two 32-MAC fp16 chains per gate, flushed to fp32. ----
        float acc[3] = {0.f, 0.f, 0.f};
        if (active) {
            if (t > 0) {
#pragma unroll
                for (int half = 0; half < 2; half++) {
                    const int base = half * 4;
                    __half2 s[3];
                    {
                        uint4 p = sH[(base + 0) * 32 + lane];
                        uint4 q = sH[(base + 1) * 32 + lane];
                        __half2 a0 = u2h2(p.x), a1 = u2h2(p.y), a2 = u2h2(p.z), a3 = u2h2(p.w);
                        __half2 b0 = u2h2(q.x), b1 = u2h2(q.y), b2 = u2h2(q.z), b3 = u2h2(q.w);
#pragma unroll
                        for (int g = 0; g < 3; g++) {
                            __half2 t0 = __hmul2(w[g][base + 0][0], a0);
                            t0 = __hfma2(w[g][base + 0][1], a1, t0);
                            t0 = __hfma2(w[g][base + 0][2], a2, t0);
                            t0 = __hfma2(w[g][base + 0][3], a3, t0);
                            t0 = __hfma2(w[g][base + 1][0], b0, t0);
                            t0 = __hfma2(w[g][base + 1][1], b1, t0);
                            t0 = __hfma2(w[g][base + 1][2], b2, t0);
                            t0 = __hfma2(w[g][base + 1][3], b3, t0);
                            s[g] = t0;
                        }
                    }
                    {
                        uint4 p = sH[(base + 2) * 32 + lane];
                        uint4 q = sH[(base + 3) * 32 + lane];
                        __half2 a0 = u2h2(p.x), a1 = u2h2(p.y), a2 = u2h2(p.z), a3 = u2h2(p.w);
                        __half2 b0 = u2h2(q.x), b1 = u2h2(q.y), b2 = u2h2(q.z), b3 = u2h2(q.w);
#pragma unroll
                        for (int g = 0; g < 3; g++) {
                            __half2 t0 = s[g];
                            t0 = __hfma2(w[g][base + 2][0], a0, t0);
                            t0 = __hfma2(w[g][base + 2][1], a1, t0);
                            t0 = __hfma2(w[g][base + 2][2], a2, t0);
                            t0 = __hfma2(w[g][base + 2][3], a3, t0);
                            t0 = __hfma2(w[g][base + 3][0], b0, t0);
                            t0 = __hfma2(w[g][base + 3][1], b1, t0);
                            t0 = __hfma2(w[g][base + 3][2], b2, t0);
                            t0 = __hfma2(w[g][base + 3][3], b3, t0);
                            float2 f = __half22float2(t0);   // flush every 32 MACs
                            acc[g] += f.x + f.y;
                        }
                    }
                }
            }

            // ---- butterfly reduce over 32 lanes ----
#pragma unroll
            for (int off = 16; off; off >>= 1) {
#pragma unroll
                for (int g = 0; g < 3; g++)
                    acc[g] += __shfl_xor_sync(0xffffffffu, acc[g], off);
            }

            // ---- gates + state update (lane 0, MUFU fast path) ----
            if (lane == 0) {
                float rg = fsig(ir + bir + acc[0]);
                float zg = fsig(iz + biz + acc[1]);
                float ng = ftanh(inn + bin + rg * (acc[2] + bhn));
                float hn = (1.0f - zg) * ng + zg * h_own;
                h_own = hn;
                out_ptr[0] = hn;
                g_h16[(t + 1) & 1][j] = __float2half(hn);
                if (t == L_SEQ - 1) {
                    size_t base = (size_t)L_SEQ * H_DIM;
                    if ((long long)(base + j) < out_elems)          out[base + j] = hn;
                    if ((long long)(base + H_DIM + j) < out_elems)  out[base + H_DIM + j] = hn;
                }
            }
        }
        __syncthreads();   // all h stores done; also guards sH reuse

        // ---- arrive ----
        if (tid == 0) {
            asm volatile("red.release.gpu.global.add.u32 [%0], %1;"
                         :: "l"(&g_sync), "r"(1u) : "memory");
        }

        // ---- rotate gi pipeline ----
        ir = nir; iz = niz; inn = ninn;
        gi_ptr  += G3H;
        out_ptr += H_DIM;
    }
}

// ============================================================
extern "C" void kernel_launch(void* const* d_in, const int* in_sizes, int n_in,
                              void* d_out, int out_size) {
    const float* x    = (const float*)d_in[0];
    const float* w_ih = (const float*)d_in[1];
    const float* w_hh = (const float*)d_in[2];
    const float* b_ih = (const float*)d_in[3];
    const float* b_hh = (const float*)d_in[4];
    float* out = (float*)d_out;

    const int nx8 = L_SEQ * H_DIM / 8;       // 524288
    const int nw8 = G3H * H_DIM / 8;         // 1572864
    cvt_x_kernel<<<(nx8 + 255) / 256, 256>>>(x);
    cvt_w_kernel<<<(nw8 + 255) / 256, 256>>>(w_ih);
    gemm_gi_kernel<<<dim3(G3H / GN, L_SEQ / GM), 256>>>();
    gru_kernel<<<NCTA, TPB>>>(w_hh, b_ih, b_hh, out, out_size);
}

// round 17
// speedup vs baseline: 1.0443x; 1.0443x over previous
#include <cuda_runtime.h>
#include <cuda_fp16.h>
#include <mma.h>
#include <math.h>

using namespace nvcuda;

#define L_SEQ 2048
#define H_DIM 2048
#define G3H   6144
#define NCTA  128
#define TPB   512     // 16 warps; warp w owns j = cta*16 + w

// -------- device-global scratch (no allocations allowed) --------
__device__ float g_gi[(size_t)L_SEQ * G3H];        // 48 MB: raw x@W_ih^T (bias added in kernel B)
__device__ __align__(16) __half g_h16[2][H_DIM];   // double-buffered fp16 h
__device__ unsigned int g_sync;                    // monotonic arrival counter
__device__ __align__(16) __half g_x16[(size_t)L_SEQ * H_DIM];   // 8 MB fp16 x
__device__ __align__(16) __half g_w16[(size_t)G3H * H_DIM];     // 24 MB fp16 w_ih

__device__ __forceinline__ __half2 u2h2(unsigned u) {
    return *reinterpret_cast<__half2*>(&u);
}

// fast sigmoid / tanh via MUFU (ex2 + rcp), rel err ~1e-6
__device__ __forceinline__ float fsig(float x) {
    float e, r;
    asm("ex2.approx.ftz.f32 %0, %1;" : "=f"(e) : "f"(-1.4426950408889634f * x));
    asm("rcp.approx.ftz.f32 %0, %1;" : "=f"(r) : "f"(1.0f + e));
    return r;
}
__device__ __forceinline__ float ftanh(float x) {
    float e, r;
    asm("ex2.approx.ftz.f32 %0, %1;" : "=f"(e) : "f"(2.8853900817779268f * x));  // e^(2x)
    asm("rcp.approx.ftz.f32 %0, %1;" : "=f"(r) : "f"(1.0f + e));
    return 1.0f - 2.0f * r;
}

// ============================================================
// fp32 -> fp16 conversion. Device globals referenced from DEVICE
// code only (host-side __device__ symbol args was the R10/R11 bug).
// ============================================================
__device__ __forceinline__ void cvt_body(const float* __restrict__ src,
                                         __half* __restrict__ dst, int i) {
    float4 f0 = reinterpret_cast<const float4*>(src)[2 * i];
    float4 f1 = reinterpret_cast<const float4*>(src)[2 * i + 1];
    __half2 h0 = __floats2half2_rn(f0.x, f0.y);
    __half2 h1 = __floats2half2_rn(f0.z, f0.w);
    __half2 h2 = __floats2half2_rn(f1.x, f1.y);
    __half2 h3 = __floats2half2_rn(f1.z, f1.w);
    uint4 v;
    v.x = *reinterpret_cast<unsigned*>(&h0);
    v.y = *reinterpret_cast<unsigned*>(&h1);
    v.z = *reinterpret_cast<unsigned*>(&h2);
    v.w = *reinterpret_cast<unsigned*>(&h3);
    reinterpret_cast<uint4*>(dst)[i] = v;
}

__global__ void cvt_x_kernel(const float* __restrict__ src) {
    int i = blockIdx.x * blockDim.x + threadIdx.x;
    if (i == 0) g_sync = 0u;
    if (i < L_SEQ * H_DIM / 8) cvt_body(src, g_x16, i);
}

__global__ void cvt_w_kernel(const float* __restrict__ src) {
    int i = blockIdx.x * blockDim.x + threadIdx.x;
    if (i < G3H * H_DIM / 8) cvt_body(src, g_w16, i);
}

// ============================================================
// Kernel A: tensor-core GEMM via wmma (R12 layout), now with a
// register-buffered 2-stage pipeline: each iteration stores the
// prefetched tile to SMEM, issues the NEXT tile's global loads,
// then runs the mma block while those loads are in flight.
// g_gi[t][c] = sum_k x16[t][k] * w16[c][k]   (raw product, no bias)
// ============================================================
#define GM 128
#define GN 64
#define GK 32
#define GP (GK + 8)   // SMEM pitch in halfs

__global__ void __launch_bounds__(256) gemm_gi_kernel() {
    __shared__ __half Asm[GM][GP];
    __shared__ __half Bsm[GN][GP];

    const int bm = blockIdx.y * GM;      // time rows
    const int bn = blockIdx.x * GN;      // gate cols
    const int tid  = threadIdx.x;
    const int warp = tid >> 5;
    const int wm = warp >> 1;            // 0..3
    const int wn = warp & 1;             // 0..1

    wmma::fragment<wmma::accumulator, 16, 16, 16, float> fc[2][2];
#pragma unroll
    for (int i = 0; i < 2; i++)
#pragma unroll
        for (int jn = 0; jn < 2; jn++)
            wmma::fill_fragment(fc[i][jn], 0.0f);

    const int arow = tid >> 1, acolh = (tid & 1) * 16;   // A: 128 rows x 32 halfs
    const int brow = tid >> 2, bcolh = (tid & 3) * 8;    // B: 64 rows x 32 halfs
    const __half* aptr = &g_x16[(size_t)(bm + arow) * H_DIM + acolh];
    const __half* bptr = &g_w16[(size_t)(bn + brow) * H_DIM + bcolh];

    // ---- pipeline prologue: load tile k0=0 into registers ----
    uint4 ra0 = reinterpret_cast<const uint4*>(aptr)[0];
    uint4 ra1 = reinterpret_cast<const uint4*>(aptr)[1];
    uint4 rb0 = reinterpret_cast<const uint4*>(bptr)[0];

    for (int k0 = 0; k0 < H_DIM; k0 += GK) {
        // ---- stage prefetched tile into SMEM ----
        *reinterpret_cast<uint4*>(&Asm[arow][acolh])     = ra0;
        *reinterpret_cast<uint4*>(&Asm[arow][acolh + 8]) = ra1;
        *reinterpret_cast<uint4*>(&Bsm[brow][bcolh])     = rb0;
        __syncthreads();

        // ---- issue NEXT tile's global loads (fly during mma) ----
        if (k0 + GK < H_DIM) {
            const __half* an = aptr + k0 + GK;
            const __half* bn2 = bptr + k0 + GK;
            ra0 = reinterpret_cast<const uint4*>(an)[0];
            ra1 = reinterpret_cast<const uint4*>(an)[1];
            rb0 = reinterpret_cast<const uint4*>(bn2)[0];
        }

#pragma unroll
        for (int kk = 0; kk < GK; kk += 16) {
            wmma::fragment<wmma::matrix_a, 16, 16, 16, __half, wmma::row_major> fa[2];
            wmma::fragment<wmma::matrix_b, 16, 16, 16, __half, wmma::col_major> fb[2];
#pragma unroll
            for (int i = 0; i < 2; i++)
                wmma::load_matrix_sync(fa[i], &Asm[wm * 32 + i * 16][kk], GP);
#pragma unroll
            for (int jn = 0; jn < 2; jn++)
                wmma::load_matrix_sync(fb[jn], &Bsm[wn * 32 + jn * 16][kk], GP);
#pragma unroll
            for (int i = 0; i < 2; i++)
#pragma unroll
                for (int jn = 0; jn < 2; jn++)
                    wmma::mma_sync(fc[i][jn], fa[i], fb[jn], fc[i][jn]);
        }
        __syncthreads();
    }

#pragma unroll
    for (int i = 0; i < 2; i++)
#pragma unroll
        for (int jn = 0; jn < 2; jn++) {
            int row = bm + wm * 32 + i * 16;
            int col = bn + wn * 32 + jn * 16;
            wmma::store_matrix_sync(&g_gi[(size_t)row * G3H + col], fc[i][jn],
                                    G3H, wmma::mem_row_major);
        }
}

// ============================================================
// Kernel B: persistent GRU recurrence — byte-exact R15 (the 4625us
// best): 128 CTAs x 512 threads, register weights, SMEM h-stage,
// MUFU gates, two 32-MAC fp16 chains, gi pipelined one step ahead.
// ============================================================
__global__ void __launch_bounds__(TPB, 1) gru_kernel(const float* __restrict__ w_hh,
                                                     const float* __restrict__ b_ih,
                                                     const float* __restrict__ b_hh,
                                                     float* __restrict__ out,
                                                     int out_elems) {
    __shared__ uint4 sH[H_DIM / 8];     // 2048 halfs = 4KB

    const int tid  = threadIdx.x;
    const int warp = tid >> 5;
    const int lane = tid & 31;
    const int j    = blockIdx.x * 16 + warp;

    // ---- prologue: 3 rows of W_hh into 96 half2 registers ----
    __half2 w[3][8][4];
#pragma unroll
    for (int g = 0; g < 3; g++) {
        const float* wr = w_hh + (size_t)(g * H_DIM + j) * H_DIM;
#pragma unroll
        for (int i = 0; i < 8; i++) {
            int k = i * 256 + lane * 8;
            float4 a = *reinterpret_cast<const float4*>(wr + k);
            float4 b = *reinterpret_cast<const float4*>(wr + k + 4);
            w[g][i][0] = __floats2half2_rn(a.x, a.y);
            w[g][i][1] = __floats2half2_rn(a.z, a.w);
            w[g][i][2] = __floats2half2_rn(b.x, b.y);
            w[g][i][3] = __floats2half2_rn(b.z, b.w);
        }
    }

    float h_own = 0.0f;
    // lane-0 bias registers: r,z get b_ih+b_hh; n gets b_ih only,
    // with b_hh_n kept inside the reset-gate product (torch semantics).
    float bir = 0.f, biz = 0.f, bin = 0.f, bhn = 0.f;
    if (lane == 0) {
        bir = b_ih[j]             + b_hh[j];
        biz = b_ih[H_DIM + j]     + b_hh[H_DIM + j];
        bin = b_ih[2 * H_DIM + j];
        bhn = b_hh[2 * H_DIM + j];
    }
    const float* gi_ptr  = g_gi + j;
    float*       out_ptr = out + j;

    // ---- gi pipeline prologue: load step 0's values ----
    float ir = 0.f, iz = 0.f, inn = 0.f;
    if (lane == 0) {
        ir  = gi_ptr[0];
        iz  = gi_ptr[H_DIM];
        inn = gi_ptr[2 * H_DIM];
    }

    for (int t = 0; t < L_SEQ; t++) {
        // ---- issue NEXT step's gi loads (consumed next iteration) ----
        float nir = 0.f, niz = 0.f, ninn = 0.f;
        if (lane == 0 && t + 1 < L_SEQ) {
            const float* np = gi_ptr + G3H;
            nir  = np[0];
            niz  = np[H_DIM];
            ninn = np[2 * H_DIM];
        }

        if (t > 0) {
            // ---- chip-wide wait for step t's h (simple tid0 poll) ----
            if (tid == 0) {
                unsigned target = (unsigned)t << 7;    // t * NCTA
                unsigned v;
                do {
                    asm volatile("ld.acquire.gpu.global.u32 %0, [%1];"
                                 : "=r"(v) : "l"(&g_sync) : "memory");
                } while (v < target);
            }
            __syncthreads();
            // ---- stage h into SMEM: 256 lanes x uint4 = 4KB ----
            if (tid < H_DIM / 8)
                sH[tid] = __ldcg(reinterpret_cast<const uint4*>(&g_h16[t & 1][0]) + tid);
            __syncthreads();
        }

        // ---- matvec: 3 rows, weights in regs, h from SMEM.
        //      Two 32-MAC fp16 chains per gate, flushed to fp32. ----
        float acc[3] = {0.f, 0.f, 0.f};
        if (t > 0) {
#pragma unroll
            for (int half = 0; half < 2; half++) {
                const int base = half * 4;
                __half2 s[3];
                {
                    uint4 p = sH[(base + 0) * 32 + lane];
                    uint4 q = sH[(base + 1) * 32 + lane];
                    __half2 a0 = u2h2(p.x), a1 = u2h2(p.y), a2 = u2h2(p.z), a3 = u2h2(p.w);
                    __half2 b0 = u2h2(q.x), b1 = u2h2(q.y), b2 = u2h2(q.z), b3 = u2h2(q.w);
#pragma unroll
                    for (int g = 0; g < 3; g++) {
                        __half2 t0 = __hmul2(w[g][base + 0][0], a0);
                        t0 = __hfma2(w[g][base + 0][1], a1, t0);
                        t0 = __hfma2(w[g][base + 0][2], a2, t0);
                        t0 = __hfma2(w[g][base + 0][3], a3, t0);
                        t0 = __hfma2(w[g][base + 1][0], b0, t0);
                        t0 = __hfma2(w[g][base + 1][1], b1, t0);
                        t0 = __hfma2(w[g][base + 1][2], b2, t0);
                        t0 = __hfma2(w[g][base + 1][3], b3, t0);
                        s[g] = t0;
                    }
                }
                {
                    uint4 p = sH[(base + 2) * 32 + lane];
                    uint4 q = sH[(base + 3) * 32 + lane];
                    __half2 a0 = u2h2(p.x), a1 = u2h2(p.y), a2 = u2h2(p.z), a3 = u2h2(p.w);
                    __half2 b0 = u2h2(q.x), b1 = u2h2(q.y), b2 = u2h2(q.z), b3 = u2h2(q.w);
#pragma unroll
                    for (int g = 0; g < 3; g++) {
                        __half2 t0 = s[g];
                        t0 = __hfma2(w[g][base + 2][0], a0, t0);
                        t0 = __hfma2(w[g][base + 2][1], a1, t0);
                        t0 = __hfma2(w[g][base + 2][2], a2, t0);
                        t0 = __hfma2(w[g][base + 2][3], a3, t0);
                        t0 = __hfma2(w[g][base + 3][0], b0, t0);
                        t0 = __hfma2(w[g][base + 3][1], b1, t0);
                        t0 = __hfma2(w[g][base + 3][2], b2, t0);
                        t0 = __hfma2(w[g][base + 3][3], b3, t0);
                        float2 f = __half22float2(t0);   // flush every 32 MACs
                        acc[g] += f.x + f.y;
                    }
                }
            }
        }

        // ---- butterfly reduce over 32 lanes ----
#pragma unroll
        for (int off = 16; off; off >>= 1) {
#pragma unroll
            for (int g = 0; g < 3; g++)
                acc[g] += __shfl_xor_sync(0xffffffffu, acc[g], off);
        }

        // ---- gates + state update (lane 0, MUFU fast path) ----
        if (lane == 0) {
            float rg = fsig(ir + bir + acc[0]);
            float zg = fsig(iz + biz + acc[1]);
            float ng = ftanh(inn + bin + rg * (acc[2] + bhn));
            float hn = (1.0f - zg) * ng + zg * h_own;
            h_own = hn;
            out_ptr[0] = hn;
            g_h16[(t + 1) & 1][j] = __float2half(hn);
            if (t == L_SEQ - 1) {
                size_t base = (size_t)L_SEQ * H_DIM;
                if ((long long)(base + j) < out_elems)          out[base + j] = hn;
                if ((long long)(base + H_DIM + j) < out_elems)  out[base + H_DIM + j] = hn;
            }
        }
        __syncthreads();   // all h stores done; also guards sH reuse

        // ---- arrive ----
        if (tid == 0) {
            asm volatile("red.release.gpu.global.add.u32 [%0], %1;"
                         :: "l"(&g_sync), "r"(1u) : "memory");
        }

        // ---- rotate gi pipeline ----
        ir = nir; iz = niz; inn = ninn;
        gi_ptr  += G3H;
        out_ptr += H_DIM;
    }
}

// ============================================================
extern "C" void kernel_launch(void* const* d_in, const int* in_sizes, int n_in,
                              void* d_out, int out_size) {
    const float* x    = (const float*)d_in[0];
    const float* w_ih = (const float*)d_in[1];
    const float* w_hh = (const float*)d_in[2];
    const float* b_ih = (const float*)d_in[3];
    const float* b_hh = (const float*)d_in[4];
    float* out = (float*)d_out;

    const int nx8 = L_SEQ * H_DIM / 8;       // 524288
    const int nw8 = G3H * H_DIM / 8;         // 1572864
    cvt_x_kernel<<<(nx8 + 255) / 256, 256>>>(x);
    cvt_w_kernel<<<(nw8 + 255) / 256, 256>>>(w_ih);
    gemm_gi_kernel<<<dim3(G3H / GN, L_SEQ / GM), 256>>>();
    gru_kernel<<<NCTA, TPB>>>(w_hh, b_ih, b_hh, out, out_size);
}